// round 2
// baseline (speedup 1.0000x reference)
#include <cuda_runtime.h>
#include <stdint.h>

// Problem constants (fixed by the dataset problem).
#define HH 112
#define WW 112
#define MAXB 4   // scratch sized for up to 4 batches

// Per-pixel winner key: high 32 = order-preserving encoded depth,
// low 32 = ~triangle_index (equal depth -> smaller index wins, matching argmax).
// 0 means "uncovered". Zero-initialized at module load; phase B re-zeros after
// consuming, so the invariant holds across graph replays.
__device__ unsigned long long g_keys[MAXB * HH * WW];

// Software grid barrier state (all blocks resident: grid <= 148 SMs).
__device__ unsigned int g_count = 0;
__device__ unsigned int g_gen   = 0;

__device__ __forceinline__ unsigned int fenc(float f) {
    unsigned int u = __float_as_uint(f);
    return (u & 0x80000000u) ? ~u : (u | 0x80000000u);
}

__global__ void __launch_bounds__(256, 1)
fused_raster(const float* __restrict__ vertices,
             const float* __restrict__ colors,
             const int*   __restrict__ triangles,
             float* __restrict__ out,
             int B, int ntri, int nver, int nblocks) {
    const int tid   = blockIdx.x * blockDim.x + threadIdx.x;
    const int nwork = B * ntri;

    // ---------------- Phase A: scatter raster ----------------
    if (tid < nwork) {
        int b = tid / ntri;
        int t = tid - b * ntri;

        int i0 = triangles[t];
        int i1 = triangles[ntri + t];
        int i2 = triangles[2 * ntri + t];

        const float* V = vertices + (size_t)b * 3 * nver;
        float x0 = V[i0],            x1 = V[i1],            x2 = V[i2];
        float y0 = V[nver + i0],     y1 = V[nver + i1],     y2 = V[nver + i2];
        float z0 = V[2 * nver + i0], z1 = V[2 * nver + i1], z2 = V[2 * nver + i2];

        float depth = ((z0 + z1) + z2) / 3.0f;

        float xmin = fminf(fminf(x0, x1), x2);
        float xmax = fmaxf(fmaxf(x0, x1), x2);
        float ymin = fminf(fminf(y0, y1), y2);
        float ymax = fmaxf(fmaxf(y0, y1), y2);

        // Match reference: max(ceil(min),0), min(floor(max), dim-1) in float, then cast.
        int umin = (int)fmaxf(ceilf(xmin), 0.0f);
        int umax = (int)fminf(floorf(xmax), (float)(WW - 1));
        int vmin = (int)fmaxf(ceilf(ymin), 0.0f);
        int vmax = (int)fminf(floorf(ymax), (float)(HH - 1));

        if (umin <= umax && vmin <= vmax) {
            unsigned long long key =
                ((unsigned long long)fenc(depth) << 32) |
                (unsigned int)(~(unsigned int)t);
            unsigned long long* base = g_keys + (size_t)b * HH * WW;
            for (int v = vmin; v <= vmax; ++v) {
                unsigned long long* row = base + (size_t)v * WW;
                for (int u = umin; u <= umax; ++u) {
                    atomicMax(&row[u], key);
                }
            }
        }
    }

    // ---------------- Grid barrier (epoch-based; wrap-safe) ----------------
    __syncthreads();
    if (threadIdx.x == 0) {
        unsigned int my_gen = atomicAdd(&g_gen, 0u);   // read before arriving
        __threadfence();                               // order phase-A atomics
        unsigned int ticket = atomicAdd(&g_count, 1u);
        if (ticket == (unsigned int)nblocks - 1u) {
            g_count = 0u;                              // reset for next replay
            __threadfence();
            atomicAdd(&g_gen, 1u);                     // release
        } else {
            while (atomicAdd(&g_gen, 0u) == my_gen) { }
        }
        __threadfence();
    }
    __syncthreads();

    // ---------------- Phase B: resolve + reset ----------------
    const int npix = B * HH * WW;
    if (tid < npix) {
        int b   = tid / (HH * WW);
        int pix = tid - b * (HH * WW);

        unsigned long long key = __ldcg(&g_keys[tid]);  // L2 read (atomics live in L2)
        g_keys[tid] = 0ull;                             // restore invariant for next replay

        float mask = 0.0f, c0 = 0.0f, c1 = 0.0f, c2 = 0.0f;
        if (key != 0ull) {
            mask = 1.0f;
            int t = (int)(~(unsigned int)(key & 0xffffffffu));
            int i0 = triangles[t];
            int i1 = triangles[ntri + t];
            int i2 = triangles[2 * ntri + t];
            const float* C = colors + (size_t)b * 3 * nver;
            c0 = ((C[i0] + C[i1]) + C[i2]) / 3.0f;
            c1 = ((C[nver + i0] + C[nver + i1]) + C[nver + i2]) / 3.0f;
            c2 = ((C[2 * nver + i0] + C[2 * nver + i1]) + C[2 * nver + i2]) / 3.0f;
        }

        // Output layout: face_mask [B,1,H,W] then image [B,3,H,W], flattened.
        out[(size_t)b * HH * WW + pix] = mask;
        float* img = out + (size_t)B * HH * WW;
        img[((size_t)b * 3 + 0) * HH * WW + pix] = c0;
        img[((size_t)b * 3 + 1) * HH * WW + pix] = c1;
        img[((size_t)b * 3 + 2) * HH * WW + pix] = c2;
    }
}

extern "C" void kernel_launch(void* const* d_in, const int* in_sizes, int n_in,
                              void* d_out, int out_size) {
    const float* vertices  = (const float*)d_in[0];
    const float* colors    = (const float*)d_in[1];
    const int*   triangles = (const int*)d_in[2];

    int ntri = in_sizes[2] / 3;
    int B    = out_size / (4 * HH * WW);
    int nver = in_sizes[0] / (3 * B);
    float* out = (float*)d_out;

    int npix    = B * HH * WW;                  // 25088 for B=2
    int threads = 256;
    int nblocks = (npix + threads - 1) / threads;  // 98 blocks < 148 SMs: all resident

    fused_raster<<<nblocks, threads>>>(vertices, colors, triangles, out,
                                       B, ntri, nver, nblocks);
}

// round 3
// speedup vs baseline: 1.0269x; 1.0269x over previous
#include <cuda_runtime.h>
#include <stdint.h>

// Problem constants (fixed by the dataset problem).
#define HH 112
#define WW 112
#define MAXB 4   // scratch sized for up to 4 batches

// Per-pixel winner key: high 32 = order-preserving encoded depth,
// low 32 = ~triangle_index (equal depth -> smaller index wins, matching argmax).
// 0 means "uncovered". Zero-initialized at module load; phase B re-zeros after
// consuming, so the invariant holds across graph replays.
__device__ unsigned long long g_keys[MAXB * HH * WW];

// Software grid barrier state (all blocks resident: grid <= 148 SMs).
__device__ unsigned int g_count = 0;
__device__ unsigned int g_gen   = 0;

__device__ __forceinline__ unsigned int fenc(float f) {
    unsigned int u = __float_as_uint(f);
    return (u & 0x80000000u) ? ~u : (u | 0x80000000u);
}

__global__ void __launch_bounds__(256, 1)
fused_raster(const float* __restrict__ vertices,
             const float* __restrict__ colors,
             const int*   __restrict__ triangles,
             float* __restrict__ out,
             int B, int ntri, int nver, int nblocks) {
    const int tid   = blockIdx.x * blockDim.x + threadIdx.x;
    const int nwork = B * ntri;

    // ---------------- Phase A: scatter raster ----------------
    if (tid < nwork) {
        int b = tid / ntri;
        int t = tid - b * ntri;

        int i0 = __ldg(&triangles[t]);
        int i1 = __ldg(&triangles[ntri + t]);
        int i2 = __ldg(&triangles[2 * ntri + t]);

        const float* V = vertices + (size_t)b * 3 * nver;
        float x0 = __ldg(&V[i0]),            x1 = __ldg(&V[i1]),            x2 = __ldg(&V[i2]);
        float y0 = __ldg(&V[nver + i0]),     y1 = __ldg(&V[nver + i1]),     y2 = __ldg(&V[nver + i2]);
        float z0 = __ldg(&V[2 * nver + i0]), z1 = __ldg(&V[2 * nver + i1]), z2 = __ldg(&V[2 * nver + i2]);

        float depth = ((z0 + z1) + z2) / 3.0f;

        float xmin = fminf(fminf(x0, x1), x2);
        float xmax = fmaxf(fmaxf(x0, x1), x2);
        float ymin = fminf(fminf(y0, y1), y2);
        float ymax = fmaxf(fmaxf(y0, y1), y2);

        // Match reference: max(ceil(min),0), min(floor(max), dim-1) in float, then cast.
        int umin = (int)fmaxf(ceilf(xmin), 0.0f);
        int umax = (int)fminf(floorf(xmax), (float)(WW - 1));
        int vmin = (int)fmaxf(ceilf(ymin), 0.0f);
        int vmax = (int)fminf(floorf(ymax), (float)(HH - 1));

        if (umin <= umax && vmin <= vmax) {
            unsigned long long key =
                ((unsigned long long)fenc(depth) << 32) |
                (unsigned int)(~(unsigned int)t);
            unsigned long long* base = g_keys + (size_t)b * HH * WW;
            for (int v = vmin; v <= vmax; ++v) {
                unsigned long long* row = base + (size_t)v * WW;
                for (int u = umin; u <= umax; ++u) {
                    atomicMax(&row[u], key);
                }
            }
        }
    }

    // ---------------- Grid barrier (load-poll, epoch-based, wrap-safe) ------
    __syncthreads();
    if (threadIdx.x == 0) {
        volatile unsigned int* vgen = &g_gen;
        unsigned int my_gen = *vgen;                   // read BEFORE arriving
        __threadfence();                               // order phase-A atomics
        unsigned int ticket = atomicAdd(&g_count, 1u);
        if (ticket == (unsigned int)nblocks - 1u) {
            g_count = 0u;                              // all arrived; reset for next replay
            __threadfence();
            atomicAdd(&g_gen, 1u);                     // release
        } else {
            // Passive poll: plain L2 loads (no RMW serialization) + backoff.
            while (*vgen == my_gen) { __nanosleep(64); }
        }
        __threadfence();
    }
    __syncthreads();

    // ---------------- Phase B: resolve + reset ----------------
    const int npix = B * HH * WW;
    if (tid < npix) {
        int b   = tid / (HH * WW);
        int pix = tid - b * (HH * WW);

        unsigned long long key = __ldcg(&g_keys[tid]);  // L2 read (atomics live in L2)
        g_keys[tid] = 0ull;                             // restore invariant for next replay

        float mask = 0.0f, c0 = 0.0f, c1 = 0.0f, c2 = 0.0f;
        if (key != 0ull) {
            mask = 1.0f;
            int t = (int)(~(unsigned int)(key & 0xffffffffu));
            int i0 = __ldg(&triangles[t]);
            int i1 = __ldg(&triangles[ntri + t]);
            int i2 = __ldg(&triangles[2 * ntri + t]);
            const float* C = colors + (size_t)b * 3 * nver;
            c0 = ((__ldg(&C[i0]) + __ldg(&C[i1])) + __ldg(&C[i2])) / 3.0f;
            c1 = ((__ldg(&C[nver + i0]) + __ldg(&C[nver + i1])) + __ldg(&C[nver + i2])) / 3.0f;
            c2 = ((__ldg(&C[2 * nver + i0]) + __ldg(&C[2 * nver + i1])) + __ldg(&C[2 * nver + i2])) / 3.0f;
        }

        // Output layout: face_mask [B,1,H,W] then image [B,3,H,W], flattened.
        out[(size_t)b * HH * WW + pix] = mask;
        float* img = out + (size_t)B * HH * WW;
        img[((size_t)b * 3 + 0) * HH * WW + pix] = c0;
        img[((size_t)b * 3 + 1) * HH * WW + pix] = c1;
        img[((size_t)b * 3 + 2) * HH * WW + pix] = c2;
    }
}

extern "C" void kernel_launch(void* const* d_in, const int* in_sizes, int n_in,
                              void* d_out, int out_size) {
    const float* vertices  = (const float*)d_in[0];
    const float* colors    = (const float*)d_in[1];
    const int*   triangles = (const int*)d_in[2];

    int ntri = in_sizes[2] / 3;
    int B    = out_size / (4 * HH * WW);
    int nver = in_sizes[0] / (3 * B);
    float* out = (float*)d_out;

    int npix    = B * HH * WW;                      // 25088 for B=2
    int threads = 256;
    int nblocks = (npix + threads - 1) / threads;   // 98 blocks < 148 SMs: all resident

    fused_raster<<<nblocks, threads>>>(vertices, colors, triangles, out,
                                       B, ntri, nver, nblocks);
}